// round 4
// baseline (speedup 1.0000x reference)
#include <cuda_runtime.h>

// Fused: out = LeakyReLU( [x_up, LeakyReLU(gather(x_down)@W_lin + b_lin)] @ W_fus + b_fus )
// Shapes: B=4, N_down=16384, N_up=65536, C_down=256, C_up=128, C_out=128.
//
// One block = 64 output rows x 128 cols. 256 threads, each computes a 4x8 tile.
// Phase 1: gathered GEMM (K=256) -> Ts[64][128] in smem (LeakyReLU applied).
// Phase 2: GEMM with K=256 split: k<128 streams x_up tiles, k>=128 reads Ts.
//
// NOTE: up_idx is int32 on device (JAX x64 disabled coerces int64 -> int32).

#define BM 64
#define BN 128
#define BK 16
#define TM 4
#define TN 8
#define THREADS 256

#define N_UP    65536
#define N_DOWN  16384
#define C_DOWN  256
#define C_UP    128

__global__ __launch_bounds__(THREADS, 2)
void upsample_fused_kernel(
    const float* __restrict__ x_down,   // [B, N_DOWN, C_DOWN]
    const float* __restrict__ x_up,     // [B, N_UP, C_UP]
    const int*   __restrict__ up_idx,   // [B, N_UP, 1]  (int32)
    const float* __restrict__ W_lin,    // [C_DOWN, C_UP]
    const float* __restrict__ b_lin,    // [C_UP]
    const float* __restrict__ W_fus,    // [2*C_UP, C_UP]
    const float* __restrict__ b_fus,    // [C_UP]
    float* __restrict__ out)            // [B, N_UP, C_UP]
{
    __shared__ float As[BK][68];        // staged A chunk, [k][m] (padded rows)
    __shared__ float Bs[BK][BN];        // staged weight chunk [k][col]
    __shared__ float Ts[BM][BN + 1];    // phase-1 result tile (padded)
    __shared__ long long rowoff[BM];    // gathered row element-offsets into x_down

    const int t = threadIdx.x;
    const long long row0 = (long long)blockIdx.x * BM;  // global row in [0, B*N_UP)

    // Precompute gathered row offsets for this tile
    if (t < BM) {
        long long n = row0 + t;
        long long b = n / N_UP;
        long long idx = (long long)up_idx[n];
        if (idx < 0) idx = 0;                  // defensive clamp
        if (idx >= N_DOWN) idx = N_DOWN - 1;
        rowoff[t] = (b * N_DOWN + idx) * C_DOWN;
    }
    __syncthreads();

    const int tn = t & 15;   // 0..15  -> cols tn*8 .. tn*8+7
    const int tm = t >> 4;   // 0..15  -> rows tm*4 .. tm*4+3
    const int c0 = tn * TN;
    const int r0 = tm * TM;

    float acc[TM][TN];
#pragma unroll
    for (int i = 0; i < TM; i++)
#pragma unroll
        for (int j = 0; j < TN; j++) acc[i][j] = 0.f;

    // ---------------- Phase 1: Ts = LeakyReLU(gather(x_down) @ W_lin + b_lin)
    for (int k0 = 0; k0 < C_DOWN; k0 += BK) {
        // stage gathered A: 64 rows x 16 k  (thread t: kk = t&15, rows t>>4 + 16i)
#pragma unroll
        for (int i = 0; i < 4; i++) {
            int m = (t >> 4) + i * 16;
            int kk = t & 15;
            As[kk][m] = x_down[rowoff[m] + k0 + kk];
        }
        // stage W_lin chunk: 16 x 128
#pragma unroll
        for (int i = 0; i < 8; i++) {
            int e = t + i * 256;
            int kk = e >> 7;
            int col = e & 127;
            Bs[kk][col] = W_lin[(k0 + kk) * C_UP + col];
        }
        __syncthreads();

#pragma unroll
        for (int kk = 0; kk < BK; kk++) {
            float a0 = As[kk][r0 + 0];
            float a1 = As[kk][r0 + 1];
            float a2 = As[kk][r0 + 2];
            float a3 = As[kk][r0 + 3];
            float4 bq0 = *(const float4*)&Bs[kk][c0];
            float4 bq1 = *(const float4*)&Bs[kk][c0 + 4];
            float bv[TN] = {bq0.x, bq0.y, bq0.z, bq0.w, bq1.x, bq1.y, bq1.z, bq1.w};
#pragma unroll
            for (int j = 0; j < TN; j++) {
                acc[0][j] = fmaf(a0, bv[j], acc[0][j]);
                acc[1][j] = fmaf(a1, bv[j], acc[1][j]);
                acc[2][j] = fmaf(a2, bv[j], acc[2][j]);
                acc[3][j] = fmaf(a3, bv[j], acc[3][j]);
            }
        }
        __syncthreads();
    }

    // epilogue 1: bias + LeakyReLU(0.1) -> Ts
    {
        float4 blq0 = *(const float4*)&b_lin[c0];
        float4 blq1 = *(const float4*)&b_lin[c0 + 4];
        float bl[TN] = {blq0.x, blq0.y, blq0.z, blq0.w, blq1.x, blq1.y, blq1.z, blq1.w};
#pragma unroll
        for (int i = 0; i < TM; i++) {
#pragma unroll
            for (int j = 0; j < TN; j++) {
                float v = acc[i][j] + bl[j];
                v = (v >= 0.f) ? v : 0.1f * v;
                Ts[r0 + i][c0 + j] = v;
                acc[i][j] = 0.f;   // reset for phase 2
            }
        }
    }
    __syncthreads();

    // ---------------- Phase 2 part A: k in [0,128) from x_up
    for (int k0 = 0; k0 < C_UP; k0 += BK) {
#pragma unroll
        for (int i = 0; i < 4; i++) {
            int m = (t >> 4) + i * 16;
            int kk = t & 15;
            As[kk][m] = x_up[(row0 + m) * C_UP + k0 + kk];
        }
#pragma unroll
        for (int i = 0; i < 8; i++) {
            int e = t + i * 256;
            int kk = e >> 7;
            int col = e & 127;
            Bs[kk][col] = W_fus[(k0 + kk) * C_UP + col];
        }
        __syncthreads();

#pragma unroll
        for (int kk = 0; kk < BK; kk++) {
            float a0 = As[kk][r0 + 0];
            float a1 = As[kk][r0 + 1];
            float a2 = As[kk][r0 + 2];
            float a3 = As[kk][r0 + 3];
            float4 bq0 = *(const float4*)&Bs[kk][c0];
            float4 bq1 = *(const float4*)&Bs[kk][c0 + 4];
            float bv[TN] = {bq0.x, bq0.y, bq0.z, bq0.w, bq1.x, bq1.y, bq1.z, bq1.w};
#pragma unroll
            for (int j = 0; j < TN; j++) {
                acc[0][j] = fmaf(a0, bv[j], acc[0][j]);
                acc[1][j] = fmaf(a1, bv[j], acc[1][j]);
                acc[2][j] = fmaf(a2, bv[j], acc[2][j]);
                acc[3][j] = fmaf(a3, bv[j], acc[3][j]);
            }
        }
        __syncthreads();
    }

    // ---------------- Phase 2 part B: k in [128,256) from Ts (smem)
    for (int k0 = C_UP; k0 < 2 * C_UP; k0 += BK) {
#pragma unroll
        for (int i = 0; i < 8; i++) {
            int e = t + i * 256;
            int kk = e >> 7;
            int col = e & 127;
            Bs[kk][col] = W_fus[(k0 + kk) * C_UP + col];
        }
        __syncthreads();

        const int kb = k0 - C_UP;
#pragma unroll
        for (int kk = 0; kk < BK; kk++) {
            float a0 = Ts[r0 + 0][kb + kk];
            float a1 = Ts[r0 + 1][kb + kk];
            float a2 = Ts[r0 + 2][kb + kk];
            float a3 = Ts[r0 + 3][kb + kk];
            float4 bq0 = *(const float4*)&Bs[kk][c0];
            float4 bq1 = *(const float4*)&Bs[kk][c0 + 4];
            float bv[TN] = {bq0.x, bq0.y, bq0.z, bq0.w, bq1.x, bq1.y, bq1.z, bq1.w};
#pragma unroll
            for (int j = 0; j < TN; j++) {
                acc[0][j] = fmaf(a0, bv[j], acc[0][j]);
                acc[1][j] = fmaf(a1, bv[j], acc[1][j]);
                acc[2][j] = fmaf(a2, bv[j], acc[2][j]);
                acc[3][j] = fmaf(a3, bv[j], acc[3][j]);
            }
        }
        __syncthreads();
    }

    // epilogue 2: bias + LeakyReLU -> out
    {
        float4 bfq0 = *(const float4*)&b_fus[c0];
        float4 bfq1 = *(const float4*)&b_fus[c0 + 4];
        float bf[TN] = {bfq0.x, bfq0.y, bfq0.z, bfq0.w, bfq1.x, bfq1.y, bfq1.z, bfq1.w};
#pragma unroll
        for (int i = 0; i < TM; i++) {
            float vout[TN];
#pragma unroll
            for (int j = 0; j < TN; j++) {
                float v = acc[i][j] + bf[j];
                vout[j] = (v >= 0.f) ? v : 0.1f * v;
            }
            float* orow = out + (row0 + r0 + i) * C_UP + c0;
            *(float4*)(orow)     = make_float4(vout[0], vout[1], vout[2], vout[3]);
            *(float4*)(orow + 4) = make_float4(vout[4], vout[5], vout[6], vout[7]);
        }
    }
}

extern "C" void kernel_launch(void* const* d_in, const int* in_sizes, int n_in,
                              void* d_out, int out_size) {
    const float* x_down = (const float*)d_in[0];
    const float* x_up   = (const float*)d_in[1];
    const int*   up_idx = (const int*)d_in[2];
    const float* W_lin  = (const float*)d_in[3];
    const float* b_lin  = (const float*)d_in[4];
    const float* W_fus  = (const float*)d_in[5];
    const float* b_fus  = (const float*)d_in[6];
    float* out = (float*)d_out;

    const long long total_rows = 4LL * N_UP;           // 262144
    const int blocks = (int)(total_rows / BM);         // 4096

    upsample_fused_kernel<<<blocks, THREADS>>>(
        x_down, x_up, up_idx, W_lin, b_lin, W_fus, b_fus, out);
}

// round 6
// speedup vs baseline: 3.8674x; 3.8674x over previous
#include <cuda_runtime.h>
#include <cuda_bf16.h>
#include <cstdint>

// Fused (HMMA mma.sync bf16, 3-term split for fp32-grade accuracy):
// out = LeakyReLU([x_up, LeakyReLU(gather(x_down)@W_lin + b_lin)] @ W_fus + b_fus)
// B=4, N_down=16384, N_up=65536, C_down=256, C_up=128, C_out=128.
// NOTE: harness ptxas targets sm_103 (no 'a') -> tcgen05 unavailable; use mma.sync.

#define N_UP    65536
#define N_DOWN  16384
#define C_UP    128

#define M_TILE  128
#define GRID    2048
#define THREADS 256

#define SWZ(x) ((x) ^ ((((uint32_t)(x)) >> 3) & 0x70))

// ---------------- SMEM layout (dynamic, bytes) ----------------
#define OFF_ROW  0                       // int rowoff[128]
#define OFF_BL   512
#define OFF_BF   1024
#define OFF_W0H  2048
#define OFF_W0L  (OFF_W0H + 16384)
#define OFF_W1H  (OFF_W0L + 16384)
#define OFF_W1L  (OFF_W1H + 16384)
#define OFF_A0H  (OFF_W1L + 16384)
#define OFF_A0L  (OFF_A0H + 16384)
#define OFF_A1H  (OFF_A0L + 16384)
#define OFF_A1L  (OFF_A1H + 16384)
#define OFF_T0H  (OFF_A1L + 16384)
#define OFF_T1H  (OFF_T0H + 16384)
#define OFF_T0L  (OFF_T1H + 16384)
#define OFF_T1L  (OFF_T0L + 16384)
#define SMEM_TOTAL (OFF_T1L + 16384)     // 198656

// ---------------- device scratch ----------------
// Pre-split, pre-swizzled weight tile images: [layer][split][k-chunk][16KB]
// Image layout: [n 0..127][k 0..63] bf16, 128B rows, SW128 swizzled.
__device__ __align__(16) unsigned char gW[2][2][4][16384];
// Pre-split x_down (bf16 hi/lo), row-major [B*N_DOWN, 256]
__device__ __align__(16) unsigned int gXd_hi[8388608];
__device__ __align__(16) unsigned int gXd_lo[8388608];

// ---------------- helpers ----------------
__device__ __forceinline__ uint32_t smem_u32(const void* p) {
    uint32_t a;
    asm("{ .reg .u64 t; cvta.to.shared.u64 t, %1; cvt.u32.u64 %0, t; }" : "=r"(a) : "l"(p));
    return a;
}
__device__ __forceinline__ float bf16r(float x) {
    return __bfloat162float(__float2bfloat16(x));
}
__device__ __forceinline__ uint32_t pack_bf16x2(float lo, float hi) {
    uint32_t d;
    asm("cvt.rn.bf16x2.f32 %0, %1, %2;" : "=r"(d) : "f"(hi), "f"(lo));
    return d;
}
__device__ __forceinline__ void ldmx4(uint32_t* r, uint32_t a) {
    asm volatile("ldmatrix.sync.aligned.m8n8.x4.shared.b16 {%0,%1,%2,%3}, [%4];"
                 : "=r"(r[0]), "=r"(r[1]), "=r"(r[2]), "=r"(r[3]) : "r"(a));
}
__device__ __forceinline__ void mma_bf16(float* c, const uint32_t* a, uint32_t b0, uint32_t b1) {
    asm volatile("mma.sync.aligned.m16n8k16.row.col.f32.bf16.bf16.f32 "
                 "{%0,%1,%2,%3}, {%4,%5,%6,%7}, {%8,%9}, {%0,%1,%2,%3};"
                 : "+f"(c[0]), "+f"(c[1]), "+f"(c[2]), "+f"(c[3])
                 : "r"(a[0]), "r"(a[1]), "r"(a[2]), "r"(a[3]), "r"(b0), "r"(b1));
}
__device__ __forceinline__ void cp16(uint32_t dst, const void* src) {
    asm volatile("cp.async.cg.shared.global [%0], [%1], 16;" :: "r"(dst), "l"(src) : "memory");
}
__device__ __forceinline__ void cp_commit() {
    asm volatile("cp.async.commit_group;" ::: "memory");
}
__device__ __forceinline__ void cp_wait0() {
    asm volatile("cp.async.wait_group 0;" ::: "memory");
}

// ---------------- prep kernels ----------------
__global__ void prep_weights(const float* __restrict__ W_lin, const float* __restrict__ W_fus) {
    int tid = blockIdx.x * blockDim.x + threadIdx.x;
    for (int e = tid; e < 2 * 128 * 256; e += gridDim.x * blockDim.x) {
        int L = e >> 15;
        int r = e & 32767;
        int n = r >> 8;          // output col (N), 0..127
        int k = r & 255;         // K, 0..255
        const float* W = L ? W_fus : W_lin;
        float w = W[k * 128 + n];
        float h = bf16r(w);
        float l = w - h;
        int c = k >> 6, kk = k & 63;
        uint32_t a = SWZ((uint32_t)(n * 128 + kk * 2));
        *(unsigned short*)&gW[L][0][c][a] = __bfloat16_as_ushort(__float2bfloat16(h));
        *(unsigned short*)&gW[L][1][c][a] = __bfloat16_as_ushort(__float2bfloat16(l));
    }
}

__global__ void prep_xdown(const float* __restrict__ xd) {
    size_t stride = (size_t)gridDim.x * blockDim.x;
    for (size_t i = (size_t)blockIdx.x * blockDim.x + threadIdx.x; i < 16777216u / 4; i += stride) {
        float4 v = ((const float4*)xd)[i];
        float hx = bf16r(v.x), hy = bf16r(v.y), hz = bf16r(v.z), hw = bf16r(v.w);
        ((uint2*)gXd_hi)[i] = make_uint2(pack_bf16x2(hx, hy), pack_bf16x2(hz, hw));
        ((uint2*)gXd_lo)[i] = make_uint2(pack_bf16x2(v.x - hx, v.y - hy),
                                         pack_bf16x2(v.z - hz, v.w - hw));
    }
}

// ---------------- staging ----------------
__device__ __forceinline__ void stage_W(uint32_t sb, int offH, int offL, int layer, int chunk, int t) {
    const char* srcH = (const char*)&gW[layer][0][chunk][0];
    const char* srcL = (const char*)&gW[layer][1][chunk][0];
#pragma unroll
    for (int i = 0; i < 4; i++) {
        int o = (t + 256 * i) * 16;
        cp16(sb + offH + o, srcH + o);
        cp16(sb + offL + o, srcL + o);
    }
}

__device__ __forceinline__ void stage_A_gather(uint32_t sb, int offH, int offL,
                                               const int* rowoff, int chunk, int t) {
    int srow = t >> 1, shalf = t & 1;
    size_t eoff = (size_t)rowoff[srow] + 64 * chunk + 32 * shalf;
    const char* sh = (const char*)gXd_hi + eoff * 2;
    const char* sl = (const char*)gXd_lo + eoff * 2;
#pragma unroll
    for (int i = 0; i < 4; i++) {
        uint32_t d = SWZ((uint32_t)(srow * 128 + 64 * shalf + 16 * i));
        cp16(sb + offH + d, sh + 16 * i);
        cp16(sb + offL + d, sl + 16 * i);
    }
}

// ---------------- per-chunk compute: acc += A(128x64) * W(64x128)^T slice ----------------
__device__ __forceinline__ void compute_chunk(
    uint32_t sb, int offAH, int offAL, int offWH, int offWL,
    float acc[2][8][4], int wm, int wn, int aRow, int aKoff, int bRow, int bKoff)
{
#pragma unroll
    for (int ks = 0; ks < 4; ks++) {
        const int kb = 16 * ks;
        uint32_t ah[2][4], al[2][4];
#pragma unroll
        for (int mi = 0; mi < 2; mi++) {
            uint32_t off = (uint32_t)((32 * wm + 16 * mi + aRow) * 128 + (kb + aKoff) * 2);
            ldmx4(ah[mi], sb + offAH + SWZ(off));
            ldmx4(al[mi], sb + offAL + SWZ(off));
        }
#pragma unroll
        for (int np = 0; np < 4; np++) {
            uint32_t boff = (uint32_t)((64 * wn + 16 * np + bRow) * 128 + (kb + bKoff) * 2);
            uint32_t bh[4], bl[4];
            ldmx4(bh, sb + offWH + SWZ(boff));
            ldmx4(bl, sb + offWL + SWZ(boff));
#pragma unroll
            for (int mi = 0; mi < 2; mi++) {
                mma_bf16(acc[mi][2 * np],     ah[mi], bh[0], bh[1]);
                mma_bf16(acc[mi][2 * np],     ah[mi], bl[0], bl[1]);
                mma_bf16(acc[mi][2 * np],     al[mi], bh[0], bh[1]);
                mma_bf16(acc[mi][2 * np + 1], ah[mi], bh[2], bh[3]);
                mma_bf16(acc[mi][2 * np + 1], ah[mi], bl[2], bl[3]);
                mma_bf16(acc[mi][2 * np + 1], al[mi], bh[2], bh[3]);
            }
        }
    }
}

// ---------------- main fused kernel ----------------
__global__ __launch_bounds__(THREADS, 1)
void upsample_hmma_kernel(
    const float* __restrict__ x_up,    // [B*N_UP, 128]
    const int*   __restrict__ up_idx,  // [B*N_UP]
    const float* __restrict__ b_lin,
    const float* __restrict__ b_fus,
    float* __restrict__ out)           // [B*N_UP, 128]
{
    extern __shared__ char smem[];
    const uint32_t sb = smem_u32(smem);
    const int t = threadIdx.x;
    const int lane = t & 31;
    const int wid = t >> 5;
    const int wm = wid >> 1;          // 0..3: rows 32*wm..+31
    const int wn = wid & 1;           // 0..1: cols 64*wn..+63
    const int row0 = blockIdx.x * M_TILE;

    int*   rowoff = (int*)(smem + OFF_ROW);
    float* sBl = (float*)(smem + OFF_BL);
    float* sBf = (float*)(smem + OFF_BF);

    if (t < 128) {
        int r = row0 + t;
        int b = r >> 16;
        int idx = up_idx[r];
        if (idx < 0) idx = 0;
        if (idx >= N_DOWN) idx = N_DOWN - 1;
        rowoff[t] = (b * N_DOWN + idx) * 256;
        sBl[t] = b_lin[t];
        sBf[t] = b_fus[t];
    }
    __syncthreads();

    // ldmatrix lane address components
    const int aRow  = (lane < 16) ? lane : (lane - 16);
    const int aKoff = (lane < 16) ? 0 : 8;
    const int bRow  = (lane & 7) + ((lane >> 4) << 3);
    const int bKoff = ((lane >> 3) & 1) * 8;

    const int fg = lane >> 2;          // fragment row group 0..7
    const int ft = lane & 3;           // fragment col pair 0..3

    float acc[2][8][4];
#pragma unroll
    for (int mi = 0; mi < 2; mi++)
#pragma unroll
        for (int ni = 0; ni < 8; ni++)
#pragma unroll
            for (int q = 0; q < 4; q++) acc[mi][ni][q] = 0.f;

    const int offWH[2] = {OFF_W0H, OFF_W1H};
    const int offWL[2] = {OFF_W0L, OFF_W1L};
    const int offAH[2] = {OFF_A0H, OFF_A1H};
    const int offAL[2] = {OFF_A0L, OFF_A1L};

    // prologue: stage chunk 0
    stage_W(sb, OFF_W0H, OFF_W0L, 0, 0, t);
    stage_A_gather(sb, OFF_A0H, OFF_A0L, rowoff, 0, t);
    cp_commit();

    // ===== Phase 1: D1 = gather(x_down) @ W_lin =====
    for (int c = 0; c < 4; c++) {
        cp_wait0();
        __syncthreads();
        if (c < 3) {
            int nb = (c + 1) & 1;
            stage_W(sb, offWH[nb], offWL[nb], 0, c + 1, t);
            stage_A_gather(sb, offAH[nb], offAL[nb], rowoff, c + 1, t);
            cp_commit();
        } else {
            stage_W(sb, OFF_W0H, OFF_W0L, 1, 0, t);  // W_fus chunk 0 -> buf0
            cp_commit();
        }
        int p = c & 1;
        compute_chunk(sb, offAH[p], offAL[p], offWH[p], offWL[p],
                      acc, wm, wn, aRow, aKoff, bRow, bKoff);
    }

    // epilogue 1: bias + LeakyReLU -> T images (smem), split hi/lo; reset acc
    {
        const int offTH = wn ? OFF_T1H : OFF_T0H;
        const int offTL = wn ? OFF_T1L : OFF_T0L;
#pragma unroll
        for (int mi = 0; mi < 2; mi++) {
#pragma unroll
            for (int ni = 0; ni < 8; ni++) {
                int col = 64 * wn + 8 * ni + ft * 2;   // global T col (k of phase 2b)
                int kloc = col & 63;
                float bl0 = sBl[col], bl1 = sBl[col + 1];
                int r0r = 32 * wm + 16 * mi + fg;
                float v0 = acc[mi][ni][0] + bl0;  v0 = (v0 >= 0.f) ? v0 : 0.1f * v0;
                float v1 = acc[mi][ni][1] + bl1;  v1 = (v1 >= 0.f) ? v1 : 0.1f * v1;
                float v2 = acc[mi][ni][2] + bl0;  v2 = (v2 >= 0.f) ? v2 : 0.1f * v2;
                float v3 = acc[mi][ni][3] + bl1;  v3 = (v3 >= 0.f) ? v3 : 0.1f * v3;
                float h0 = bf16r(v0), h1 = bf16r(v1), h2 = bf16r(v2), h3 = bf16r(v3);
                uint32_t a0 = SWZ((uint32_t)(r0r * 128 + kloc * 2));
                uint32_t a1 = SWZ((uint32_t)((r0r + 8) * 128 + kloc * 2));
                *(uint32_t*)(smem + offTH + a0) = pack_bf16x2(h0, h1);
                *(uint32_t*)(smem + offTL + a0) = pack_bf16x2(v0 - h0, v1 - h1);
                *(uint32_t*)(smem + offTH + a1) = pack_bf16x2(h2, h3);
                *(uint32_t*)(smem + offTL + a1) = pack_bf16x2(v2 - h2, v3 - h3);
                acc[mi][ni][0] = acc[mi][ni][1] = acc[mi][ni][2] = acc[mi][ni][3] = 0.f;
            }
        }
    }

    // ===== Phase 2a: x_up chunks (W_fus k-rows 0..127) =====
    for (int c = 0; c < 2; c++) {
        cp_wait0();
        __syncthreads();
        // synchronous A staging from x_up with inline bf16 split
        {
            int srow = t >> 1, shalf = t & 1;
            const float4* src = (const float4*)(x_up + (size_t)(row0 + srow) * C_UP
                                                + 64 * c + 32 * shalf);
            int p = c & 1;
#pragma unroll
            for (int i = 0; i < 8; i++) {
                float4 v = src[i];
                float hx = bf16r(v.x), hy = bf16r(v.y), hz = bf16r(v.z), hw = bf16r(v.w);
                uint32_t a = SWZ((uint32_t)(srow * 128 + 64 * shalf + 8 * i));
                *(uint32_t*)(smem + offAH[p] + a)     = pack_bf16x2(hx, hy);
                *(uint32_t*)(smem + offAH[p] + a + 4) = pack_bf16x2(hz, hw);
                *(uint32_t*)(smem + offAL[p] + a)     = pack_bf16x2(v.x - hx, v.y - hy);
                *(uint32_t*)(smem + offAL[p] + a + 4) = pack_bf16x2(v.z - hz, v.w - hw);
            }
        }
        // next W chunk
        {
            int nb = (c + 1) & 1;
            stage_W(sb, offWH[nb], offWL[nb], 1, c + 1, t);   // fus chunk 1 then 2
            cp_commit();
        }
        __syncthreads();   // A staged by all threads before ldmatrix
        int p = c & 1;
        compute_chunk(sb, offAH[p], offAL[p], offWH[p], offWL[p],
                      acc, wm, wn, aRow, aKoff, bRow, bKoff);
    }

    // ===== Phase 2b: T chunks (W_fus k-rows 128..255) =====
    for (int c = 0; c < 2; c++) {
        cp_wait0();
        __syncthreads();
        if (c == 0) {
            stage_W(sb, OFF_W1H, OFF_W1L, 1, 3, t);   // fus chunk 3 -> buf1
            cp_commit();
        }
        int p = c & 1;
        int offTH = c ? OFF_T1H : OFF_T0H;
        int offTL = c ? OFF_T1L : OFF_T0L;
        compute_chunk(sb, offTH, offTL, offWH[p], offWL[p],
                      acc, wm, wn, aRow, aKoff, bRow, bKoff);
    }
    cp_wait0();  // drain any remaining group

    // ===== epilogue 2: out = LeakyReLU(D2 + b_fus) =====
#pragma unroll
    for (int mi = 0; mi < 2; mi++) {
#pragma unroll
        for (int ni = 0; ni < 8; ni++) {
            int col = 64 * wn + 8 * ni + ft * 2;
            float bf0 = sBf[col], bf1 = sBf[col + 1];
            int rg = row0 + 32 * wm + 16 * mi + fg;
            float v0 = acc[mi][ni][0] + bf0;  v0 = (v0 >= 0.f) ? v0 : 0.1f * v0;
            float v1 = acc[mi][ni][1] + bf1;  v1 = (v1 >= 0.f) ? v1 : 0.1f * v1;
            float v2 = acc[mi][ni][2] + bf0;  v2 = (v2 >= 0.f) ? v2 : 0.1f * v2;
            float v3 = acc[mi][ni][3] + bf1;  v3 = (v3 >= 0.f) ? v3 : 0.1f * v3;
            *(float2*)(out + (size_t)rg * C_UP + col)       = make_float2(v0, v1);
            *(float2*)(out + (size_t)(rg + 8) * C_UP + col) = make_float2(v2, v3);
        }
    }
}

extern "C" void kernel_launch(void* const* d_in, const int* in_sizes, int n_in,
                              void* d_out, int out_size) {
    const float* x_down = (const float*)d_in[0];
    const float* x_up   = (const float*)d_in[1];
    const int*   up_idx = (const int*)d_in[2];
    const float* W_lin  = (const float*)d_in[3];
    const float* b_lin  = (const float*)d_in[4];
    const float* W_fus  = (const float*)d_in[5];
    const float* b_fus  = (const float*)d_in[6];
    float* out = (float*)d_out;

    cudaFuncSetAttribute(upsample_hmma_kernel,
                         cudaFuncAttributeMaxDynamicSharedMemorySize, SMEM_TOTAL);

    prep_weights<<<64, 256>>>(W_lin, W_fus);
    prep_xdown<<<1024, 256>>>(x_down);
    upsample_hmma_kernel<<<GRID, THREADS, SMEM_TOTAL>>>(x_up, up_idx, b_lin, b_fus, out);
}

// round 7
// speedup vs baseline: 4.7004x; 1.2154x over previous
#include <cuda_runtime.h>
#include <cuda_bf16.h>
#include <cstdint>

// Fused (HMMA mma.sync bf16, 3-term split for fp32-grade accuracy):
// out = LeakyReLU([x_up, LeakyReLU(gather(x_down)@W_lin + b_lin)] @ W_fus + b_fus)
// Key identity: MLP(gather(x)) == gather(MLP(x))  ->  compute down-MLP once
// (65536 rows) instead of per upsampled point (262144 rows): 4x less phase-1 work.
// B=4, N_down=16384, N_up=65536, C_down=256, C_up=128, C_out=128.
// NOTE: harness ptxas targets sm_103 (no 'a') -> tcgen05 unavailable; use mma.sync.

#define N_UP    65536
#define N_DOWN  16384
#define C_UP    128

#define M_TILE  128
#define THREADS 256

#define SWZ(x) ((x) ^ ((((uint32_t)(x)) >> 3) & 0x70))

// ---------------- shared SMEM layout (both kernels, bytes) ----------------
#define OFF_B    0                        // bias[128] fp32
#define OFF_W0H  1024
#define OFF_W0L  (OFF_W0H + 16384)
#define OFF_W1H  (OFF_W0L + 16384)
#define OFF_W1L  (OFF_W1H + 16384)
#define OFF_A0H  (OFF_W1L + 16384)
#define OFF_A0L  (OFF_A0H + 16384)
#define OFF_A1H  (OFF_A0L + 16384)
#define OFF_A1L  (OFF_A1H + 16384)
#define OFF_S0   (OFF_A1L + 16384)        // fp32 staging scratch, 32KB
#define OFF_S1   (OFF_S0 + 32768)
#define SMEM_TOTAL (OFF_S1 + 32768)       // 197632

// ---------------- device scratch ----------------
// Pre-split, pre-swizzled weight tile images: [layer][split][k-chunk][16KB]
// Image layout: [n 0..127][k 0..63] bf16, 128B rows, SW128 swizzled.
__device__ __align__(16) unsigned char gW[2][2][4][16384];
// Down-MLP output y, pre-split bf16 hi/lo, row-major [B*N_DOWN][128] (uint32 = bf16x2)
__device__ __align__(16) unsigned int gY_hi[4194304];
__device__ __align__(16) unsigned int gY_lo[4194304];

// ---------------- helpers ----------------
__device__ __forceinline__ uint32_t smem_u32(const void* p) {
    uint32_t a;
    asm("{ .reg .u64 t; cvta.to.shared.u64 t, %1; cvt.u32.u64 %0, t; }" : "=r"(a) : "l"(p));
    return a;
}
__device__ __forceinline__ float bf16r(float x) {
    return __bfloat162float(__float2bfloat16(x));
}
__device__ __forceinline__ uint32_t pack_bf16x2(float lo, float hi) {
    uint32_t d;
    asm("cvt.rn.bf16x2.f32 %0, %1, %2;" : "=r"(d) : "f"(hi), "f"(lo));
    return d;
}
__device__ __forceinline__ void ldmx4(uint32_t* r, uint32_t a) {
    asm volatile("ldmatrix.sync.aligned.m8n8.x4.shared.b16 {%0,%1,%2,%3}, [%4];"
                 : "=r"(r[0]), "=r"(r[1]), "=r"(r[2]), "=r"(r[3]) : "r"(a));
}
__device__ __forceinline__ void mma_bf16(float* c, const uint32_t* a, uint32_t b0, uint32_t b1) {
    asm volatile("mma.sync.aligned.m16n8k16.row.col.f32.bf16.bf16.f32 "
                 "{%0,%1,%2,%3}, {%4,%5,%6,%7}, {%8,%9}, {%0,%1,%2,%3};"
                 : "+f"(c[0]), "+f"(c[1]), "+f"(c[2]), "+f"(c[3])
                 : "r"(a[0]), "r"(a[1]), "r"(a[2]), "r"(a[3]), "r"(b0), "r"(b1));
}
__device__ __forceinline__ void cp16(uint32_t dst, const void* src) {
    asm volatile("cp.async.cg.shared.global [%0], [%1], 16;" :: "r"(dst), "l"(src) : "memory");
}
__device__ __forceinline__ void cp_commit() {
    asm volatile("cp.async.commit_group;" ::: "memory");
}
template <int N>
__device__ __forceinline__ void cp_wait() {
    asm volatile("cp.async.wait_group %0;" :: "n"(N) : "memory");
}

// ---------------- prep ----------------
__global__ void prep_weights(const float* __restrict__ W_lin, const float* __restrict__ W_fus) {
    int tid = blockIdx.x * blockDim.x + threadIdx.x;
    for (int e = tid; e < 2 * 128 * 256; e += gridDim.x * blockDim.x) {
        int L = e >> 15;
        int r = e & 32767;
        int n = r >> 8;          // output col (N), 0..127
        int k = r & 255;         // K, 0..255
        const float* W = L ? W_fus : W_lin;
        float w = W[k * 128 + n];
        float h = bf16r(w);
        float l = w - h;
        int c = k >> 6, kk = k & 63;
        uint32_t a = SWZ((uint32_t)(n * 128 + kk * 2));
        *(unsigned short*)&gW[L][0][c][a] = __bfloat16_as_ushort(__float2bfloat16(h));
        *(unsigned short*)&gW[L][1][c][a] = __bfloat16_as_ushort(__float2bfloat16(l));
    }
}

// ---------------- staging ----------------
__device__ __forceinline__ void stage_W(uint32_t sb, int offH, int offL, int layer, int chunk, int t) {
    const char* srcH = (const char*)&gW[layer][0][chunk][0];
    const char* srcL = (const char*)&gW[layer][1][chunk][0];
#pragma unroll
    for (int i = 0; i < 4; i++) {
        int o = (t + 256 * i) * 16;
        cp16(sb + offH + o, srcH + o);
        cp16(sb + offL + o, srcL + o);
    }
}

// Raw fp32 chunk (128 rows x 64 cols) -> S scratch. rowstride_b = source row bytes.
__device__ __forceinline__ void stage_S(uint32_t sb, int offS, const float* src0,
                                        int rowstride_b, int chunk, int t) {
    int srow = t >> 1, shalf = t & 1;
    const char* src = (const char*)src0 + (size_t)srow * rowstride_b + chunk * 256 + shalf * 128;
    uint32_t dst = sb + offS + srow * 256 + shalf * 128;
#pragma unroll
    for (int i = 0; i < 8; i++) cp16(dst + 16 * i, src + 16 * i);
}

// Gather pre-split y rows (bf16) straight into swizzled A images.
__device__ __forceinline__ void stage_Yg(uint32_t sb, int offH, int offL,
                                         int yrow, int chunk, int t) {
    int srow = t >> 1, shalf = t & 1;
    size_t boff = (size_t)yrow * 256 + chunk * 128 + shalf * 64;   // bytes into gY
    const char* sh = (const char*)gY_hi + boff;
    const char* sl = (const char*)gY_lo + boff;
#pragma unroll
    for (int i = 0; i < 4; i++) {
        uint32_t d = SWZ((uint32_t)(srow * 128 + 64 * shalf + 16 * i));
        cp16(sb + offH + d, sh + 16 * i);
        cp16(sb + offL + d, sl + 16 * i);
    }
}

// Convert S (fp32 [128][64]) -> split bf16 A images (swizzled).
__device__ __forceinline__ void convert_S(char* smem, int offS, int offAH, int offAL, int t) {
    int srow = t >> 1, shalf = t & 1;
    const float4* src = (const float4*)(smem + offS + srow * 256 + shalf * 128);
#pragma unroll
    for (int i = 0; i < 8; i++) {
        float4 v = src[i];
        float hx = bf16r(v.x), hy = bf16r(v.y), hz = bf16r(v.z), hw = bf16r(v.w);
        uint32_t a = SWZ((uint32_t)(srow * 128 + 64 * shalf + 8 * i));
        *(uint32_t*)(smem + offAH + a)     = pack_bf16x2(hx, hy);
        *(uint32_t*)(smem + offAH + a + 4) = pack_bf16x2(hz, hw);
        *(uint32_t*)(smem + offAL + a)     = pack_bf16x2(v.x - hx, v.y - hy);
        *(uint32_t*)(smem + offAL + a + 4) = pack_bf16x2(v.z - hz, v.w - hw);
    }
}

// ---------------- per-chunk compute: acc += A(128x64) * W(64x128)^T ----------------
__device__ __forceinline__ void compute_chunk(
    uint32_t sb, int offAH, int offAL, int offWH, int offWL,
    float acc[2][8][4], int wm, int wn, int aRow, int aKoff, int bRow, int bKoff)
{
#pragma unroll
    for (int ks = 0; ks < 4; ks++) {
        const int kb = 16 * ks;
        uint32_t ah[2][4], al[2][4];
#pragma unroll
        for (int mi = 0; mi < 2; mi++) {
            uint32_t off = (uint32_t)((32 * wm + 16 * mi + aRow) * 128 + (kb + aKoff) * 2);
            ldmx4(ah[mi], sb + offAH + SWZ(off));
            ldmx4(al[mi], sb + offAL + SWZ(off));
        }
#pragma unroll
        for (int np = 0; np < 4; np++) {
            uint32_t boff = (uint32_t)((64 * wn + 16 * np + bRow) * 128 + (kb + bKoff) * 2);
            uint32_t bh[4], bl[4];
            ldmx4(bh, sb + offWH + SWZ(boff));
            ldmx4(bl, sb + offWL + SWZ(boff));
#pragma unroll
            for (int mi = 0; mi < 2; mi++) {
                mma_bf16(acc[mi][2 * np],     ah[mi], bh[0], bh[1]);
                mma_bf16(acc[mi][2 * np],     ah[mi], bl[0], bl[1]);
                mma_bf16(acc[mi][2 * np],     al[mi], bh[0], bh[1]);
                mma_bf16(acc[mi][2 * np + 1], ah[mi], bh[2], bh[3]);
                mma_bf16(acc[mi][2 * np + 1], ah[mi], bl[2], bl[3]);
                mma_bf16(acc[mi][2 * np + 1], al[mi], bh[2], bh[3]);
            }
        }
    }
}

// ================= Kernel A: y = LeakyReLU(x_down @ W_lin + b_lin), split to gY =====
__global__ __launch_bounds__(THREADS, 1)
void down_mlp_kernel(const float* __restrict__ x_down, const float* __restrict__ b_lin) {
    extern __shared__ char smem[];
    const uint32_t sb = smem_u32(smem);
    const int t = threadIdx.x;
    const int lane = t & 31;
    const int wid = t >> 5;
    const int wm = wid >> 1, wn = wid & 1;
    const int row0 = blockIdx.x * M_TILE;

    float* sB = (float*)(smem + OFF_B);
    if (t < 128) sB[t] = b_lin[t];

    const int aRow  = (lane < 16) ? lane : (lane - 16);
    const int aKoff = (lane < 16) ? 0 : 8;
    const int bRow  = (lane & 7) + ((lane >> 4) << 3);
    const int bKoff = ((lane >> 3) & 1) * 8;
    const int fg = lane >> 2, ft = lane & 3;

    float acc[2][8][4];
#pragma unroll
    for (int mi = 0; mi < 2; mi++)
#pragma unroll
        for (int ni = 0; ni < 8; ni++)
#pragma unroll
            for (int q = 0; q < 4; q++) acc[mi][ni][q] = 0.f;

    const int offWH[2] = {OFF_W0H, OFF_W1H};
    const int offWL[2] = {OFF_W0L, OFF_W1L};
    const int offAH[2] = {OFF_A0H, OFF_A1H};
    const int offAL[2] = {OFF_A0L, OFF_A1L};
    const int offS[2]  = {OFF_S0, OFF_S1};
    const float* xrow0 = x_down + (size_t)row0 * 256;

    stage_W(sb, OFF_W0H, OFF_W0L, 0, 0, t);
    stage_S(sb, OFF_S0, xrow0, 1024, 0, t);
    cp_commit();                                      // G0
    stage_W(sb, OFF_W1H, OFF_W1L, 0, 1, t);
    stage_S(sb, OFF_S1, xrow0, 1024, 1, t);
    cp_commit();                                      // G1

#pragma unroll
    for (int c = 0; c < 4; c++) {
        if (c < 3) cp_wait<1>(); else cp_wait<0>();
        __syncthreads();
        int p = c & 1;
        convert_S(smem, offS[p], offAH[p], offAL[p], t);
        __syncthreads();
        compute_chunk(sb, offAH[p], offAL[p], offWH[p], offWL[p],
                      acc, wm, wn, aRow, aKoff, bRow, bKoff);
        __syncthreads();
        if (c + 2 < 4) {
            stage_W(sb, offWH[p], offWL[p], 0, c + 2, t);
            stage_S(sb, offS[p], xrow0, 1024, c + 2, t);
            cp_commit();
        }
    }

    // epilogue: bias + LeakyReLU, split hi/lo -> gY (row-major, uint32 = bf16x2)
#pragma unroll
    for (int mi = 0; mi < 2; mi++) {
#pragma unroll
        for (int ni = 0; ni < 8; ni++) {
            int col = 64 * wn + 8 * ni + ft * 2;
            float b0 = sB[col], b1 = sB[col + 1];
            int rg = row0 + 32 * wm + 16 * mi + fg;
            float v0 = acc[mi][ni][0] + b0;  v0 = (v0 >= 0.f) ? v0 : 0.1f * v0;
            float v1 = acc[mi][ni][1] + b1;  v1 = (v1 >= 0.f) ? v1 : 0.1f * v1;
            float v2 = acc[mi][ni][2] + b0;  v2 = (v2 >= 0.f) ? v2 : 0.1f * v2;
            float v3 = acc[mi][ni][3] + b1;  v3 = (v3 >= 0.f) ? v3 : 0.1f * v3;
            float h0 = bf16r(v0), h1 = bf16r(v1), h2 = bf16r(v2), h3 = bf16r(v3);
            gY_hi[rg * 64 + (col >> 1)]       = pack_bf16x2(h0, h1);
            gY_lo[rg * 64 + (col >> 1)]       = pack_bf16x2(v0 - h0, v1 - h1);
            gY_hi[(rg + 8) * 64 + (col >> 1)] = pack_bf16x2(h2, h3);
            gY_lo[(rg + 8) * 64 + (col >> 1)] = pack_bf16x2(v2 - h2, v3 - h3);
        }
    }
}

// ================= Kernel B: out = LeakyReLU([x_up, gather(y)] @ W_fus + b_fus) =====
__global__ __launch_bounds__(THREADS, 1)
void upsample_kernel(
    const float* __restrict__ x_up,    // [B*N_UP, 128]
    const int*   __restrict__ up_idx,  // [B*N_UP]
    const float* __restrict__ b_fus,
    float* __restrict__ out)           // [B*N_UP, 128]
{
    extern __shared__ char smem[];
    const uint32_t sb = smem_u32(smem);
    const int t = threadIdx.x;
    const int lane = t & 31;
    const int wid = t >> 5;
    const int wm = wid >> 1, wn = wid & 1;
    const int row0 = blockIdx.x * M_TILE;

    float* sB = (float*)(smem + OFF_B);
    if (t < 128) sB[t] = b_fus[t];

    // this thread's gather row (register-resident; staging is per-thread)
    const int srow = t >> 1;
    int r = row0 + srow;
    int idx = up_idx[r];
    if (idx < 0) idx = 0;
    if (idx >= N_DOWN) idx = N_DOWN - 1;
    const int yrow = (r >> 16) * N_DOWN + idx;

    const int aRow  = (lane < 16) ? lane : (lane - 16);
    const int aKoff = (lane < 16) ? 0 : 8;
    const int bRow  = (lane & 7) + ((lane >> 4) << 3);
    const int bKoff = ((lane >> 3) & 1) * 8;
    const int fg = lane >> 2, ft = lane & 3;

    float acc[2][8][4];
#pragma unroll
    for (int mi = 0; mi < 2; mi++)
#pragma unroll
        for (int ni = 0; ni < 8; ni++)
#pragma unroll
            for (int q = 0; q < 4; q++) acc[mi][ni][q] = 0.f;

    // prologue: 4 cp.async groups in flight
    stage_W(sb, OFF_W0H, OFF_W0L, 1, 2, t);        // W_fus k-rows 128..191 (y part)
    stage_Yg(sb, OFF_A0H, OFF_A0L, yrow, 0, t);    // y k 0..63
    cp_commit();                                    // G0
    stage_W(sb, OFF_W1H, OFF_W1L, 1, 3, t);        // W_fus k-rows 192..255
    stage_Yg(sb, OFF_A1H, OFF_A1L, yrow, 1, t);    // y k 64..127
    cp_commit();                                    // G1
    stage_S(sb, OFF_S0, x_up + (size_t)row0 * 128, 512, 0, t);
    cp_commit();                                    // G2
    stage_S(sb, OFF_S1, x_up + (size_t)row0 * 128, 512, 1, t);
    cp_commit();                                    // G3

    // step 0: y chunk 0
    cp_wait<3>();
    __syncthreads();
    compute_chunk(sb, OFF_A0H, OFF_A0L, OFF_W0H, OFF_W0L,
                  acc, wm, wn, aRow, aKoff, bRow, bKoff);
    __syncthreads();
    stage_W(sb, OFF_W0H, OFF_W0L, 1, 0, t);
    cp_commit();                                    // G4

    // step 1: y chunk 1
    cp_wait<3>();
    __syncthreads();
    compute_chunk(sb, OFF_A1H, OFF_A1L, OFF_W1H, OFF_W1L,
                  acc, wm, wn, aRow, aKoff, bRow, bKoff);
    __syncthreads();
    stage_W(sb, OFF_W1H, OFF_W1L, 1, 1, t);
    cp_commit();                                    // G5

    // step 2: x_up chunk 0
    cp_wait<2>();
    __syncthreads();
    convert_S(smem, OFF_S0, OFF_A0H, OFF_A0L, t);
    cp_wait<1>();
    __syncthreads();
    compute_chunk(sb, OFF_A0H, OFF_A0L, OFF_W0H, OFF_W0L,
                  acc, wm, wn, aRow, aKoff, bRow, bKoff);
    __syncthreads();

    // step 3: x_up chunk 1
    convert_S(smem, OFF_S1, OFF_A1H, OFF_A1L, t);
    cp_wait<0>();
    __syncthreads();
    compute_chunk(sb, OFF_A1H, OFF_A1L, OFF_W1H, OFF_W1L,
                  acc, wm, wn, aRow, aKoff, bRow, bKoff);

    // epilogue: out = LeakyReLU(acc + b_fus)
#pragma unroll
    for (int mi = 0; mi < 2; mi++) {
#pragma unroll
        for (int ni = 0; ni < 8; ni++) {
            int col = 64 * wn + 8 * ni + ft * 2;
            float b0 = sB[col], b1 = sB[col + 1];
            int rg = row0 + 32 * wm + 16 * mi + fg;
            float v0 = acc[mi][ni][0] + b0;  v0 = (v0 >= 0.f) ? v0 : 0.1f * v0;
            float v1 = acc[mi][ni][1] + b1;  v1 = (v1 >= 0.f) ? v1 : 0.1f * v1;
            float v2 = acc[mi][ni][2] + b0;  v2 = (v2 >= 0.f) ? v2 : 0.1f * v2;
            float v3 = acc[mi][ni][3] + b1;  v3 = (v3 >= 0.f) ? v3 : 0.1f * v3;
            *(float2*)(out + (size_t)rg * C_UP + col)       = make_float2(v0, v1);
            *(float2*)(out + (size_t)(rg + 8) * C_UP + col) = make_float2(v2, v3);
        }
    }
}

extern "C" void kernel_launch(void* const* d_in, const int* in_sizes, int n_in,
                              void* d_out, int out_size) {
    const float* x_down = (const float*)d_in[0];
    const float* x_up   = (const float*)d_in[1];
    const int*   up_idx = (const int*)d_in[2];
    const float* W_lin  = (const float*)d_in[3];
    const float* b_lin  = (const float*)d_in[4];
    const float* W_fus  = (const float*)d_in[5];
    const float* b_fus  = (const float*)d_in[6];
    float* out = (float*)d_out;

    cudaFuncSetAttribute(down_mlp_kernel,
                         cudaFuncAttributeMaxDynamicSharedMemorySize, SMEM_TOTAL);
    cudaFuncSetAttribute(upsample_kernel,
                         cudaFuncAttributeMaxDynamicSharedMemorySize, SMEM_TOTAL);

    prep_weights<<<64, 256>>>(W_lin, W_fus);
    down_mlp_kernel<<<N_DOWN * 4 / M_TILE, THREADS, SMEM_TOTAL>>>(x_down, b_lin);
    upsample_kernel<<<N_UP * 4 / M_TILE, THREADS, SMEM_TOTAL>>>(x_up, up_idx, b_fus, out);
}

// round 10
// speedup vs baseline: 5.8434x; 1.2432x over previous
#include <cuda_runtime.h>
#include <cuda_bf16.h>
#include <cstdint>

// Fused (HMMA mma.sync bf16, 3-term split for fp32-grade accuracy):
// out = LeakyReLU([x_up, LeakyReLU(gather(x_down)@W_lin + b_lin)] @ W_fus + b_fus)
// Identity: MLP(gather(x)) == gather(MLP(x)) -> down-MLP computed once (4x less work).
// R8: 97KB smem -> 2 CTAs/SM for stall overlap; inline LDG->split->STS conversion.
// NOTE: harness ptxas targets sm_103 (no 'a') -> tcgen05 unavailable; use mma.sync.

#define N_UP    65536
#define N_DOWN  16384
#define C_UP    128

#define M_TILE  128
#define THREADS 256

#define SWZ(x) ((x) ^ ((((uint32_t)(x)) >> 3) & 0x70))

// ---------------- SMEM layout (bytes) ----------------
#define OFF_B    0                        // bias[128] fp32
#define OFF_WH   1024
#define OFF_WL   (OFF_WH + 16384)
#define OFF_A0H  (OFF_WL + 16384)
#define OFF_A0L  (OFF_A0H + 16384)
#define OFF_A1H  (OFF_A0L + 16384)
#define OFF_A1L  (OFF_A1H + 16384)
#define SMEM_TOTAL (OFF_A1L + 16384)      // 99328 (~97KB) -> 2 CTAs/SM

// ---------------- device scratch ----------------
// Pre-split, pre-swizzled weight tile images: [layer][split][k-chunk][16KB]
// Image layout: [n 0..127][k 0..63] bf16, 128B rows, SW128 swizzled.
__device__ __align__(16) unsigned char gW[2][2][4][16384];
// Down-MLP output y, pre-split bf16 hi/lo, row-major [B*N_DOWN][128] (uint32 = bf16x2)
__device__ __align__(16) unsigned int gY_hi[4194304];
__device__ __align__(16) unsigned int gY_lo[4194304];

// ---------------- helpers ----------------
__device__ __forceinline__ uint32_t smem_u32(const void* p) {
    uint32_t a;
    asm("{ .reg .u64 t; cvta.to.shared.u64 t, %1; cvt.u32.u64 %0, t; }" : "=r"(a) : "l"(p));
    return a;
}
__device__ __forceinline__ float bf16r(float x) {
    return __bfloat162float(__float2bfloat16(x));
}
__device__ __forceinline__ uint32_t pack_bf16x2(float lo, float hi) {
    uint32_t d;
    asm("cvt.rn.bf16x2.f32 %0, %1, %2;" : "=r"(d) : "f"(hi), "f"(lo));
    return d;
}
__device__ __forceinline__ void ldmx4(uint32_t* r, uint32_t a) {
    asm volatile("ldmatrix.sync.aligned.m8n8.x4.shared.b16 {%0,%1,%2,%3}, [%4];"
                 : "=r"(r[0]), "=r"(r[1]), "=r"(r[2]), "=r"(r[3]) : "r"(a));
}
__device__ __forceinline__ void mma_bf16(float* c, const uint32_t* a, uint32_t b0, uint32_t b1) {
    asm volatile("mma.sync.aligned.m16n8k16.row.col.f32.bf16.bf16.f32 "
                 "{%0,%1,%2,%3}, {%4,%5,%6,%7}, {%8,%9}, {%0,%1,%2,%3};"
                 : "+f"(c[0]), "+f"(c[1]), "+f"(c[2]), "+f"(c[3])
                 : "r"(a[0]), "r"(a[1]), "r"(a[2]), "r"(a[3]), "r"(b0), "r"(b1));
}
__device__ __forceinline__ void cp16(uint32_t dst, const void* src) {
    asm volatile("cp.async.cg.shared.global [%0], [%1], 16;" :: "r"(dst), "l"(src) : "memory");
}
__device__ __forceinline__ void cp_commit() {
    asm volatile("cp.async.commit_group;" ::: "memory");
}
template <int N>
__device__ __forceinline__ void cp_wait() {
    asm volatile("cp.async.wait_group %0;" :: "n"(N) : "memory");
}

// ---------------- prep ----------------
__global__ void prep_weights(const float* __restrict__ W_lin, const float* __restrict__ W_fus) {
    int tid = blockIdx.x * blockDim.x + threadIdx.x;
    for (int e = tid; e < 2 * 128 * 256; e += gridDim.x * blockDim.x) {
        int L = e >> 15;
        int r = e & 32767;
        int n = r >> 8;          // output col (N), 0..127
        int k = r & 255;         // K, 0..255
        const float* W = L ? W_fus : W_lin;
        float w = W[k * 128 + n];
        float h = bf16r(w);
        float l = w - h;
        int c = k >> 6, kk = k & 63;
        uint32_t a = SWZ((uint32_t)(n * 128 + kk * 2));
        *(unsigned short*)&gW[L][0][c][a] = __bfloat16_as_ushort(__float2bfloat16(h));
        *(unsigned short*)&gW[L][1][c][a] = __bfloat16_as_ushort(__float2bfloat16(l));
    }
}

// ---------------- staging ----------------
__device__ __forceinline__ void stage_W(uint32_t sb, int layer, int chunk, int t) {
    const char* srcH = (const char*)&gW[layer][0][chunk][0];
    const char* srcL = (const char*)&gW[layer][1][chunk][0];
#pragma unroll
    for (int i = 0; i < 4; i++) {
        int o = (t + 256 * i) * 16;
        cp16(sb + OFF_WH + o, srcH + o);
        cp16(sb + OFF_WL + o, srcL + o);
    }
}

// Gather pre-split y rows (bf16) straight into swizzled A images.
__device__ __forceinline__ void stage_Yg(uint32_t sb, int offH, int offL,
                                         int yrow, int chunk, int t) {
    int srow = t >> 1, shalf = t & 1;
    size_t boff = (size_t)yrow * 256 + chunk * 128 + shalf * 64;   // bytes into gY
    const char* sh = (const char*)gY_hi + boff;
    const char* sl = (const char*)gY_lo + boff;
#pragma unroll
    for (int i = 0; i < 4; i++) {
        uint32_t d = SWZ((uint32_t)(srow * 128 + 64 * shalf + 16 * i));
        cp16(sb + offH + d, sh + 16 * i);
        cp16(sb + offL + d, sl + 16 * i);
    }
}

// LDG fp32 chunk (row srow, 32 cols) -> split bf16 -> swizzled A images.
__device__ __forceinline__ void convert_x(char* smem, int offH, int offL,
                                          const float* src0, int rowstride_f,
                                          int chunk, int t) {
    int srow = t >> 1, shalf = t & 1;
    const float4* src = (const float4*)(src0 + (size_t)srow * rowstride_f
                                        + chunk * 64 + shalf * 32);
#pragma unroll
    for (int i = 0; i < 8; i++) {
        float4 v = src[i];
        float hx = bf16r(v.x), hy = bf16r(v.y), hz = bf16r(v.z), hw = bf16r(v.w);
        uint32_t a = SWZ((uint32_t)(srow * 128 + 64 * shalf + 8 * i));
        *(uint2*)(smem + offH + a) = make_uint2(pack_bf16x2(hx, hy), pack_bf16x2(hz, hw));
        *(uint2*)(smem + offL + a) = make_uint2(pack_bf16x2(v.x - hx, v.y - hy),
                                                pack_bf16x2(v.z - hz, v.w - hw));
    }
}

// ---------------- per-chunk compute: acc += A(128x64) * W(64x128)^T ----------------
__device__ __forceinline__ void compute_chunk(
    uint32_t sb, int offAH, int offAL,
    float acc[2][8][4], int wm, int wn, int aRow, int aKoff, int bRow, int bKoff)
{
#pragma unroll
    for (int ks = 0; ks < 4; ks++) {
        const int kb = 16 * ks;
        uint32_t ah[2][4], al[2][4];
#pragma unroll
        for (int mi = 0; mi < 2; mi++) {
            uint32_t off = (uint32_t)((32 * wm + 16 * mi + aRow) * 128 + (kb + aKoff) * 2);
            ldmx4(ah[mi], sb + offAH + SWZ(off));
            ldmx4(al[mi], sb + offAL + SWZ(off));
        }
#pragma unroll
        for (int np = 0; np < 4; np++) {
            uint32_t boff = (uint32_t)((64 * wn + 16 * np + bRow) * 128 + (kb + bKoff) * 2);
            uint32_t bh[4], bl[4];
            ldmx4(bh, sb + OFF_WH + SWZ(boff));
            ldmx4(bl, sb + OFF_WL + SWZ(boff));
#pragma unroll
            for (int mi = 0; mi < 2; mi++) {
                mma_bf16(acc[mi][2 * np],     ah[mi], bh[0], bh[1]);
                mma_bf16(acc[mi][2 * np],     ah[mi], bl[0], bl[1]);
                mma_bf16(acc[mi][2 * np],     al[mi], bh[0], bh[1]);
                mma_bf16(acc[mi][2 * np + 1], ah[mi], bh[2], bh[3]);
                mma_bf16(acc[mi][2 * np + 1], ah[mi], bl[2], bl[3]);
                mma_bf16(acc[mi][2 * np + 1], al[mi], bh[2], bh[3]);
            }
        }
    }
}

// ================= Kernel A: y = LeakyReLU(x_down @ W_lin + b_lin) -> gY =====
__global__ __launch_bounds__(THREADS, 2)
void down_mlp_kernel(const float* __restrict__ x_down, const float* __restrict__ b_lin) {
    extern __shared__ char smem[];
    const uint32_t sb = smem_u32(smem);
    const int t = threadIdx.x;
    const int lane = t & 31;
    const int wid = t >> 5;
    const int wm = wid >> 1, wn = wid & 1;
    const int row0 = blockIdx.x * M_TILE;

    float* sB = (float*)(smem + OFF_B);
    if (t < 128) sB[t] = b_lin[t];

    const int aRow  = (lane < 16) ? lane : (lane - 16);
    const int aKoff = (lane < 16) ? 0 : 8;
    const int bRow  = (lane & 7) + ((lane >> 4) << 3);
    const int bKoff = ((lane >> 3) & 1) * 8;
    const int fg = lane >> 2, ft = lane & 3;

    float acc[2][8][4];
#pragma unroll
    for (int mi = 0; mi < 2; mi++)
#pragma unroll
        for (int ni = 0; ni < 8; ni++)
#pragma unroll
            for (int q = 0; q < 4; q++) acc[mi][ni][q] = 0.f;

    const int offAH[2] = {OFF_A0H, OFF_A1H};
    const int offAL[2] = {OFF_A0L, OFF_A1L};
    const float* xrow0 = x_down + (size_t)row0 * 256;

    stage_W(sb, 0, 0, t);
    cp_commit();
    convert_x(smem, OFF_A0H, OFF_A0L, xrow0, 256, 0, t);

#pragma unroll
    for (int c = 0; c < 4; c++) {
        cp_wait<0>();
        __syncthreads();
        int p = c & 1;
        compute_chunk(sb, offAH[p], offAL[p], acc, wm, wn, aRow, aKoff, bRow, bKoff);
        __syncthreads();
        if (c < 3) {
            stage_W(sb, 0, c + 1, t);
            cp_commit();
            convert_x(smem, offAH[p ^ 1], offAL[p ^ 1], xrow0, 256, c + 1, t);
        }
    }

    // epilogue: bias + LeakyReLU, split hi/lo -> gY
#pragma unroll
    for (int mi = 0; mi < 2; mi++) {
#pragma unroll
        for (int ni = 0; ni < 8; ni++) {
            int col = 64 * wn + 8 * ni + ft * 2;
            float b0 = sB[col], b1 = sB[col + 1];
            int rg = row0 + 32 * wm + 16 * mi + fg;
            float v0 = acc[mi][ni][0] + b0;  v0 = (v0 >= 0.f) ? v0 : 0.1f * v0;
            float v1 = acc[mi][ni][1] + b1;  v1 = (v1 >= 0.f) ? v1 : 0.1f * v1;
            float v2 = acc[mi][ni][2] + b0;  v2 = (v2 >= 0.f) ? v2 : 0.1f * v2;
            float v3 = acc[mi][ni][3] + b1;  v3 = (v3 >= 0.f) ? v3 : 0.1f * v3;
            float h0 = bf16r(v0), h1 = bf16r(v1), h2 = bf16r(v2), h3 = bf16r(v3);
            gY_hi[rg * 64 + (col >> 1)]       = pack_bf16x2(h0, h1);
            gY_lo[rg * 64 + (col >> 1)]       = pack_bf16x2(v0 - h0, v1 - h1);
            gY_hi[(rg + 8) * 64 + (col >> 1)] = pack_bf16x2(h2, h3);
            gY_lo[(rg + 8) * 64 + (col >> 1)] = pack_bf16x2(v2 - h2, v3 - h3);
        }
    }
}

// ================= Kernel B: out = LeakyReLU([x_up, gather(y)] @ W_fus + b_fus) =====
__global__ __launch_bounds__(THREADS, 2)
void upsample_kernel(
    const float* __restrict__ x_up,    // [B*N_UP, 128]
    const int*   __restrict__ up_idx,  // [B*N_UP]
    const float* __restrict__ b_fus,
    float* __restrict__ out)           // [B*N_UP, 128]
{
    extern __shared__ char smem[];
    const uint32_t sb = smem_u32(smem);
    const int t = threadIdx.x;
    const int lane = t & 31;
    const int wid = t >> 5;
    const int wm = wid >> 1, wn = wid & 1;
    const int row0 = blockIdx.x * M_TILE;

    float* sB = (float*)(smem + OFF_B);
    if (t < 128) sB[t] = b_fus[t];

    // this thread's gather row
    const int srow = t >> 1;
    int r = row0 + srow;
    int idx = up_idx[r];
    if (idx < 0) idx = 0;
    if (idx >= N_DOWN) idx = N_DOWN - 1;
    const int yrow = (r >> 16) * N_DOWN + idx;

    const int aRow  = (lane < 16) ? lane : (lane - 16);
    const int aKoff = (lane < 16) ? 0 : 8;
    const int bRow  = (lane & 7) + ((lane >> 4) << 3);
    const int bKoff = ((lane >> 3) & 1) * 8;
    const int fg = lane >> 2, ft = lane & 3;

    float acc[2][8][4];
#pragma unroll
    for (int mi = 0; mi < 2; mi++)
#pragma unroll
        for (int ni = 0; ni < 8; ni++)
#pragma unroll
            for (int q = 0; q < 4; q++) acc[mi][ni][q] = 0.f;

    const float* xrow0 = x_up + (size_t)row0 * 128;

    // prologue: G0 = {y chunk 0 -> A0, W_fus chunk 2}, G1 = {y chunk 1 -> A1}
    stage_Yg(sb, OFF_A0H, OFF_A0L, yrow, 0, t);
    stage_W(sb, 1, 2, t);                 // W_fus k-rows 128..191 pairs with y k 0..63
    cp_commit();                          // G0
    stage_Yg(sb, OFF_A1H, OFF_A1L, yrow, 1, t);
    cp_commit();                          // G1

    // step 0: y chunk 0
    cp_wait<1>();                         // G0 retired
    __syncthreads();
    compute_chunk(sb, OFF_A0H, OFF_A0L, acc, wm, wn, aRow, aKoff, bRow, bKoff);
    __syncthreads();

    // step 1: y chunk 1 (W_fus chunk 3)
    stage_W(sb, 1, 3, t);
    cp_commit();
    cp_wait<0>();
    __syncthreads();
    compute_chunk(sb, OFF_A1H, OFF_A1L, acc, wm, wn, aRow, aKoff, bRow, bKoff);
    __syncthreads();

    // step 2: x_up chunk 0 (W_fus chunk 0)
    stage_W(sb, 1, 0, t);
    cp_commit();
    convert_x(smem, OFF_A0H, OFF_A0L, xrow0, 128, 0, t);
    cp_wait<0>();
    __syncthreads();
    compute_chunk(sb, OFF_A0H, OFF_A0L, acc, wm, wn, aRow, aKoff, bRow, bKoff);
    __syncthreads();

    // step 3: x_up chunk 1 (W_fus chunk 1)
    stage_W(sb, 1, 1, t);
    cp_commit();
    convert_x(smem, OFF_A1H, OFF_A1L, xrow0, 128, 1, t);
    cp_wait<0>();
    __syncthreads();
    compute_chunk(sb, OFF_A1H, OFF_A1L, acc, wm, wn, aRow, aKoff, bRow, bKoff);

    // epilogue: out = LeakyReLU(acc + b_fus)
#pragma unroll
    for (int mi = 0; mi < 2; mi++) {
#pragma unroll
        for (int ni = 0; ni < 8; ni++) {
            int col = 64 * wn + 8 * ni + ft * 2;
            float b0 = sB[col], b1 = sB[col + 1];
            int rg = row0 + 32 * wm + 16 * mi + fg;
            float v0 = acc[mi][ni][0] + b0;  v0 = (v0 >= 0.f) ? v0 : 0.1f * v0;
            float v1 = acc[mi][ni][1] + b1;  v1 = (v1 >= 0.f) ? v1 : 0.1f * v1;
            float v2 = acc[mi][ni][2] + b0;  v2 = (v2 >= 0.f) ? v2 : 0.1f * v2;
            float v3 = acc[mi][ni][3] + b1;  v3 = (v3 >= 0.f) ? v3 : 0.1f * v3;
            *(float2*)(out + (size_t)rg * C_UP + col)       = make_float2(v0, v1);
            *(float2*)(out + (size_t)(rg + 8) * C_UP + col) = make_float2(v2, v3);
        }
    }
}

extern "C" void kernel_launch(void* const* d_in, const int* in_sizes, int n_in,
                              void* d_out, int out_size) {
    const float* x_down = (const float*)d_in[0];
    const float* x_up   = (const float*)d_in[1];
    const int*   up_idx = (const int*)d_in[2];
    const float* W_lin  = (const float*)d_in[3];
    const float* b_lin  = (const float*)d_in[4];
    const float* W_fus  = (const float*)d_in[5];
    const float* b_fus  = (const float*)d_in[6];
    float* out = (float*)d_out;

    cudaFuncSetAttribute(down_mlp_kernel,
                         cudaFuncAttributeMaxDynamicSharedMemorySize, SMEM_TOTAL);
    cudaFuncSetAttribute(upsample_kernel,
                         cudaFuncAttributeMaxDynamicSharedMemorySize, SMEM_TOTAL);

    prep_weights<<<256, 256>>>(W_lin, W_fus);
    down_mlp_kernel<<<N_DOWN * 4 / M_TILE, THREADS, SMEM_TOTAL>>>(x_down, b_lin);
    upsample_kernel<<<N_UP * 4 / M_TILE, THREADS, SMEM_TOTAL>>>(x_up, up_idx, b_fus, out);
}